// round 15
// baseline (speedup 1.0000x reference)
#include <cuda_runtime.h>

// B=2, C=32, H=80, W=240, D=64. out (B, 2C, D, H, W) fp32.
// 629 MB stores, ~10 MB L2-resident loads. Store-BW bound.
// R13 = 88.2us (7.13 TB/s, 89% spec). DRAM 78% / L1 77% co-binding.
//
// Each thread handles 4 consecutive d (dbase..dbase+3) for one (c, h, w4).
// Key algebra: w0 and dbase are both multiples of 4, so s = w0-dbase is
// 4-aligned -> the y windows of all four d's live in just TWO aligned
// float4s (C = y4[q-1], A = y4[q]) and every per-d shift is a COMPILE-TIME
// shuffle (dd=0: A verbatim; dd=1/2/3: fixed C/A lane mixes).
// Per thread: 6 LDG.128 -> 16 STG.128 (vs 6 -> 4 before). x is loaded once
// per 4 d instead of once per d. Zero dynamic selects, zero divergence.

#define W4N    60
#define QCNT   9830400u     // 32*64*80*60  (c2+32 stride in float4s)
#define QD     2457600u     // QCNT/4 threads = 9600 * 256
#define PLANE  614400u      // 32*80*240    (per-batch input floats)
#define DSTR   4800u        // 80*60: float4 stride between consecutive d

__global__ __launch_bounds__(256)
void cost_volume_kernel(const float* __restrict__ x,
                        const float* __restrict__ y,
                        float* __restrict__ out)
{
    unsigned int j = blockIdx.x * 256u + threadIdx.x;   // [0, QD)

    // j -> (c, d4, h, w4)
    unsigned int row = j / W4N;
    unsigned int w4  = j - row * W4N;
    unsigned int h   = row % 80u;
    unsigned int t   = row / 80u;                // < 512
    unsigned int d4  = t & 15u;
    unsigned int c   = t >> 4;                   // < 32
    int w0    = (int)(w4 * 4u);
    int dbase = (int)(d4 * 4u);                  // d = dbase + dd

    unsigned int off = (c * 80u + h) * 240u;     // b=0 input row base (floats)
    unsigned int rb0 = off >> 2;                 // in float4s
    unsigned int rb1 = (off + PLANE) >> 2;

    // ── x: one aligned float4 per batch, reused by all 4 d ──
    const float4* x4 = reinterpret_cast<const float4*>(x);
    float4 xL0 = __ldg(x4 + rb0 + w4);
    float4 xL1 = __ldg(x4 + rb1 + w4);

    // ── y window: s = w0 - dbase (4-aligned). Need floats s-3 .. s+3,
    //    i.e. float4s q-1 (C) and q (A), clamped; garbage lanes are masked. ──
    int q  = (w0 - dbase) >> 2;                  // can be negative
    int qa = max(q, 0);
    int qc = max(q - 1, 0);
    const float4* y4 = reinterpret_cast<const float4*>(y);
    float4 A0 = __ldg(y4 + rb0 + qa);
    float4 C0 = __ldg(y4 + rb0 + qc);
    float4 A1 = __ldg(y4 + rb1 + qa);
    float4 C1 = __ldg(y4 + rb1 + qc);

    unsigned int base = ((c * 64u + (unsigned)dbase) * 80u + h) * 60u + w4;
    float4* o = reinterpret_cast<float4*>(out);

    #pragma unroll
    for (int dd = 0; dd < 4; dd++) {
        int di = dbase + dd;
        bool m0 = (w0     >= di);
        bool m1 = (w0 + 1 >= di);
        bool m2 = (w0 + 2 >= di);
        bool m3 = (w0 + 3 >= di);

        // left: masked copy of the shared x float4s
        float4 vL0 = xL0, vL1 = xL1;

        // right: compile-time shuffle of (C, A); window pos = s-dd .. s-dd+3
        float4 vR0, vR1;
        if (dd == 0) {        // r=0: A verbatim
            vR0 = A0;                         vR1 = A1;
        } else if (dd == 1) { // r=3: [C.w, A.x, A.y, A.z]
            vR0 = make_float4(C0.w, A0.x, A0.y, A0.z);
            vR1 = make_float4(C1.w, A1.x, A1.y, A1.z);
        } else if (dd == 2) { // r=2: [C.z, C.w, A.x, A.y]
            vR0 = make_float4(C0.z, C0.w, A0.x, A0.y);
            vR1 = make_float4(C1.z, C1.w, A1.x, A1.y);
        } else {              // r=1: [C.y, C.z, C.w, A.x]
            vR0 = make_float4(C0.y, C0.z, C0.w, A0.x);
            vR1 = make_float4(C1.y, C1.z, C1.w, A1.x);
        }

        if (!m0) { vL0.x = 0.0f; vL1.x = 0.0f; vR0.x = 0.0f; vR1.x = 0.0f; }
        if (!m1) { vL0.y = 0.0f; vL1.y = 0.0f; vR0.y = 0.0f; vR1.y = 0.0f; }
        if (!m2) { vL0.z = 0.0f; vL1.z = 0.0f; vR0.z = 0.0f; vR1.z = 0.0f; }
        if (!m3) { vL0.w = 0.0f; vL1.w = 0.0f; vR0.w = 0.0f; vR1.w = 0.0f; }

        unsigned int jo = base + (unsigned)dd * DSTR;
        __stcs(o + jo,             vL0);   // b=0, left  (c2 = c)
        __stcs(o + jo + QCNT,      vR0);   // b=0, right (c2 = c+32)
        __stcs(o + jo + 2u * QCNT, vL1);   // b=1, left
        __stcs(o + jo + 3u * QCNT, vR1);   // b=1, right
    }
}

extern "C" void kernel_launch(void* const* d_in, const int* in_sizes, int n_in,
                              void* d_out, int out_size)
{
    const float* x = (const float*)d_in[0];
    const float* y = (const float*)d_in[1];
    float* out = (float*)d_out;

    cost_volume_kernel<<<QD / 256, 256>>>(x, y, out);   // 9,600 blocks
}